// round 1
// baseline (speedup 1.0000x reference)
#include <cuda_runtime.h>
#include <cuda_bf16.h>
#include <cstddef>

// Problem constants
#define BSZ   4
#define TLEN  2048
#define CDIM  1024
#define NH    16
#define DH    64
#define MROWS (BSZ * TLEN)          // 8192
#define THREEC (3 * CDIM)           // 3072

// Scratch: device globals (no runtime allocation allowed)
__device__ float g_qkv[(size_t)MROWS * THREEC];   // [B*T, 3C]
__device__ float g_attn[(size_t)MROWS * CDIM];    // [B*T, C]

// ---------------------------------------------------------------------------
// SGEMM with fused bias: C[M,N] = A[M,K] @ B[K,N] + bias[N]
// 128x128x16 tile, 256 threads, 8x8 per thread. M%128==0, N%128==0, K%16==0.
// ---------------------------------------------------------------------------
__global__ __launch_bounds__(256) void sgemm_bias_kernel(
    const float* __restrict__ A, const float* __restrict__ Bm,
    const float* __restrict__ bias, float* __restrict__ C,
    int M, int N, int K)
{
    constexpr int BM = 128, BN = 128, BK = 16;
    __shared__ float As[BK][BM];
    __shared__ float Bs[BK][BN];

    const int tid = threadIdx.x;
    const int row0 = blockIdx.y * BM;
    const int col0 = blockIdx.x * BN;
    const int tx = tid & 15;        // 0..15
    const int ty = tid >> 4;        // 0..15

    float acc[8][8] = {};

    const float* Aptr = A + (size_t)row0 * K;
    const float* Bptr = Bm + col0;

    for (int k0 = 0; k0 < K; k0 += BK) {
        // Load A tile (128x16) -> As transposed [k][m]
        #pragma unroll
        for (int i = 0; i < 2; i++) {
            int f = tid + i * 256;          // 0..511 float4 index
            int r = f >> 2;                 // 0..127
            int c4 = (f & 3) * 4;           // 0,4,8,12
            float4 v = *(const float4*)(Aptr + (size_t)r * K + k0 + c4);
            As[c4 + 0][r] = v.x;
            As[c4 + 1][r] = v.y;
            As[c4 + 2][r] = v.z;
            As[c4 + 3][r] = v.w;
        }
        // Load B tile (16x128)
        #pragma unroll
        for (int i = 0; i < 2; i++) {
            int f = tid + i * 256;
            int r = f >> 5;                 // 0..15
            int c4 = (f & 31) * 4;          // 0..124
            *(float4*)&Bs[r][c4] = *(const float4*)(Bptr + (size_t)(k0 + r) * N + c4);
        }
        __syncthreads();

        #pragma unroll
        for (int k = 0; k < BK; k++) {
            float a[8], b[8];
            *(float4*)&a[0] = *(float4*)&As[k][ty * 8 + 0];
            *(float4*)&a[4] = *(float4*)&As[k][ty * 8 + 4];
            *(float4*)&b[0] = *(float4*)&Bs[k][tx * 8 + 0];
            *(float4*)&b[4] = *(float4*)&Bs[k][tx * 8 + 4];
            #pragma unroll
            for (int i = 0; i < 8; i++)
                #pragma unroll
                for (int j = 0; j < 8; j++)
                    acc[i][j] += a[i] * b[j];
        }
        __syncthreads();
    }

    // Epilogue with bias
    #pragma unroll
    for (int i = 0; i < 8; i++) {
        int r = row0 + ty * 8 + i;
        #pragma unroll
        for (int j = 0; j < 8; j += 4) {
            int c = col0 + tx * 8 + j;
            float4 v;
            v.x = acc[i][j + 0] + bias[c + 0];
            v.y = acc[i][j + 1] + bias[c + 1];
            v.z = acc[i][j + 2] + bias[c + 2];
            v.w = acc[i][j + 3] + bias[c + 3];
            *(float4*)(C + (size_t)r * N + c) = v;
        }
    }
}

// ---------------------------------------------------------------------------
// Causal flash attention, fp32, Dh=64. One thread owns one query row.
// Block = 64 threads (one 64-query tile per block).
// grid: (T/64, H, B). q-tiles scheduled in reverse for causal load balance.
// Reads g_qkv ([B*T, 3C]: q | k | v), writes g_attn ([B*T, C]).
// ---------------------------------------------------------------------------
__global__ __launch_bounds__(64) void attn_kernel()
{
    __shared__ float Ks[64][64];
    __shared__ float Vs[64][64];

    const int qt = (gridDim.x - 1) - blockIdx.x;   // reversed schedule
    const int h  = blockIdx.y;
    const int b  = blockIdx.z;
    const int t  = threadIdx.x;                    // 0..63
    const int qrow = qt * 64 + t;
    const float scale = 0.125f;                    // 1/sqrt(64)

    // Load q row into registers (pre-scaled)
    float q[64];
    const float* qptr = g_qkv + ((size_t)(b * TLEN + qrow)) * THREEC + h * DH;
    #pragma unroll
    for (int d = 0; d < 64; d += 4) {
        float4 v = *(const float4*)(qptr + d);
        q[d + 0] = v.x * scale;
        q[d + 1] = v.y * scale;
        q[d + 2] = v.z * scale;
        q[d + 3] = v.w * scale;
    }

    float O[64];
    #pragma unroll
    for (int d = 0; d < 64; d++) O[d] = 0.0f;
    float m = -1e30f;
    float l = 0.0f;

    for (int kt = 0; kt <= qt; kt++) {
        // Cooperative, coalesced K/V tile loads: 1024 float4 per tile, 16 per thread
        const float* kbase = g_qkv + ((size_t)(b * TLEN + kt * 64)) * THREEC + CDIM + h * DH;
        const float* vbase = kbase + CDIM;
        #pragma unroll
        for (int i = 0; i < 16; i++) {
            int f = i * 64 + t;           // 0..1023
            int r = f >> 4;               // 0..63
            int c = (f & 15) * 4;         // 0..60
            *(float4*)&Ks[r][c] = *(const float4*)(kbase + (size_t)r * THREEC + c);
            *(float4*)&Vs[r][c] = *(const float4*)(vbase + (size_t)r * THREEC + c);
        }
        __syncthreads();

        const int jmax = (kt == qt) ? t : 63;
        for (int j = 0; j <= jmax; j++) {
            // s = q . K[j]  (4 independent partial sums)
            float s0 = 0.f, s1 = 0.f, s2 = 0.f, s3 = 0.f;
            #pragma unroll
            for (int d = 0; d < 64; d += 16) {
                float4 k0 = *(const float4*)&Ks[j][d + 0];
                float4 k1 = *(const float4*)&Ks[j][d + 4];
                float4 k2 = *(const float4*)&Ks[j][d + 8];
                float4 k3 = *(const float4*)&Ks[j][d + 12];
                s0 += q[d + 0] * k0.x + q[d + 1] * k0.y + q[d + 2] * k0.z + q[d + 3] * k0.w;
                s1 += q[d + 4] * k1.x + q[d + 5] * k1.y + q[d + 6] * k1.z + q[d + 7] * k1.w;
                s2 += q[d + 8] * k2.x + q[d + 9] * k2.y + q[d + 10] * k2.z + q[d + 11] * k2.w;
                s3 += q[d + 12] * k3.x + q[d + 13] * k3.y + q[d + 14] * k3.z + q[d + 15] * k3.w;
            }
            float s = (s0 + s1) + (s2 + s3);

            if (s > m) {
                float alpha = __expf(m - s);
                #pragma unroll
                for (int d = 0; d < 64; d++) O[d] *= alpha;
                l *= alpha;
                m = s;
            }
            float p = __expf(s - m);
            l += p;
            #pragma unroll
            for (int d = 0; d < 64; d += 4) {
                float4 vv = *(const float4*)&Vs[j][d];
                O[d + 0] += p * vv.x;
                O[d + 1] += p * vv.y;
                O[d + 2] += p * vv.z;
                O[d + 3] += p * vv.w;
            }
        }
        __syncthreads();
    }

    const float inv = 1.0f / l;
    float* optr = g_attn + ((size_t)(b * TLEN + qrow)) * CDIM + h * DH;
    #pragma unroll
    for (int d = 0; d < 64; d += 4) {
        float4 v;
        v.x = O[d + 0] * inv;
        v.y = O[d + 1] * inv;
        v.z = O[d + 2] * inv;
        v.w = O[d + 3] * inv;
        *(float4*)(optr + d) = v;
    }
}

// ---------------------------------------------------------------------------
// kernel_launch
// Inputs (metadata order): x [B,T,C], W_qkv [C,3C], b_qkv [3C],
//                          W_proj [C,C], b_proj [C]. Output: [B,T,C] fp32.
// ---------------------------------------------------------------------------
extern "C" void kernel_launch(void* const* d_in, const int* in_sizes, int n_in,
                              void* d_out, int out_size)
{
    const float* x     = (const float*)d_in[0];
    const float* Wqkv  = (const float*)d_in[1];
    const float* bqkv  = (const float*)d_in[2];
    const float* Wproj = (const float*)d_in[3];
    const float* bproj = (const float*)d_in[4];
    float* out = (float*)d_out;

    float* qkv_ptr;
    float* attn_ptr;
    cudaGetSymbolAddress((void**)&qkv_ptr,  g_qkv);
    cudaGetSymbolAddress((void**)&attn_ptr, g_attn);

    // 1) QKV GEMM: [8192,1024] @ [1024,3072] + bias
    {
        dim3 grid(THREEC / 128, MROWS / 128);
        sgemm_bias_kernel<<<grid, 256>>>(x, Wqkv, bqkv, qkv_ptr,
                                         MROWS, THREEC, CDIM);
    }

    // 2) Causal flash attention
    {
        dim3 grid(TLEN / 64, NH, BSZ);
        attn_kernel<<<grid, 64>>>();
    }

    // 3) Projection GEMM: [8192,1024] @ [1024,1024] + bias
    {
        dim3 grid(CDIM / 128, MROWS / 128);
        sgemm_bias_kernel<<<grid, 256>>>(attn_ptr, Wproj, bproj, out,
                                         MROWS, CDIM, CDIM);
    }
}

// round 3
// speedup vs baseline: 1.3544x; 1.3544x over previous
#include <cuda_runtime.h>
#include <cuda_bf16.h>
#include <cstdint>
#include <cstddef>

// Problem constants
#define BSZ   4
#define TLEN  2048
#define CDIM  1024
#define NH    16
#define DH    64
#define MROWS (BSZ * TLEN)          // 8192
#define THREEC (3 * CDIM)           // 3072

// ---------------------------------------------------------------------------
// Scratch device globals (no runtime allocation allowed)
// ---------------------------------------------------------------------------
__device__ float g_qkv[(size_t)MROWS * THREEC];            // [B*T, 3C] fp32
__device__ __nv_bfloat16 g_x_hi[(size_t)MROWS * CDIM];     // x split
__device__ __nv_bfloat16 g_x_lo[(size_t)MROWS * CDIM];
__device__ __nv_bfloat16 g_wqkv_hi[(size_t)THREEC * CDIM]; // W_qkv^T [N,K]
__device__ __nv_bfloat16 g_wqkv_lo[(size_t)THREEC * CDIM];
__device__ __nv_bfloat16 g_wp_hi[(size_t)CDIM * CDIM];     // W_proj^T [N,K]
__device__ __nv_bfloat16 g_wp_lo[(size_t)CDIM * CDIM];
__device__ __nv_bfloat16 g_attn_hi[(size_t)MROWS * CDIM];  // attention out split
__device__ __nv_bfloat16 g_attn_lo[(size_t)MROWS * CDIM];

// ---------------------------------------------------------------------------
// Helpers
// ---------------------------------------------------------------------------
__device__ __forceinline__ uint32_t smem_u32(const void* p) {
    uint32_t a;
    asm("{ .reg .u64 t; cvta.to.shared.u64 t, %1; cvt.u32.u64 %0, t; }"
        : "=r"(a) : "l"(p));
    return a;
}

__device__ __forceinline__ void cp_async16(uint32_t saddr, const void* gaddr) {
    asm volatile("cp.async.cg.shared.global [%0], [%1], 16;"
                 :: "r"(saddr), "l"(gaddr) : "memory");
}
#define CP_COMMIT() asm volatile("cp.async.commit_group;" ::: "memory")
#define CP_WAIT(n)  asm volatile("cp.async.wait_group %0;" :: "n"(n) : "memory")

__device__ __forceinline__ void mma_bf16(float* d,
                                         const uint32_t* a, const uint32_t* b) {
    asm volatile(
        "mma.sync.aligned.m16n8k16.row.col.f32.bf16.bf16.f32 "
        "{%0,%1,%2,%3}, {%4,%5,%6,%7}, {%8,%9}, {%0,%1,%2,%3};"
        : "+f"(d[0]), "+f"(d[1]), "+f"(d[2]), "+f"(d[3])
        : "r"(a[0]), "r"(a[1]), "r"(a[2]), "r"(a[3]),
          "r"(b[0]), "r"(b[1]));
}

// ---------------------------------------------------------------------------
// Split fp32 -> (hi, lo) bf16, elementwise, vectorized
// ---------------------------------------------------------------------------
__global__ void split_kernel(const float4* __restrict__ in,
                             uint2* __restrict__ hi, uint2* __restrict__ lo, int n4)
{
    for (int i = blockIdx.x * blockDim.x + threadIdx.x; i < n4; i += gridDim.x * blockDim.x) {
        float4 v = in[i];
        __nv_bfloat16 h0 = __float2bfloat16(v.x);
        __nv_bfloat16 h1 = __float2bfloat16(v.y);
        __nv_bfloat16 h2 = __float2bfloat16(v.z);
        __nv_bfloat16 h3 = __float2bfloat16(v.w);
        __nv_bfloat16 l0 = __float2bfloat16(v.x - __bfloat162float(h0));
        __nv_bfloat16 l1 = __float2bfloat16(v.y - __bfloat162float(h1));
        __nv_bfloat16 l2 = __float2bfloat16(v.z - __bfloat162float(h2));
        __nv_bfloat16 l3 = __float2bfloat16(v.w - __bfloat162float(h3));
        uint2 H, L;
        H.x = (uint32_t)__bfloat16_as_ushort(h0) | ((uint32_t)__bfloat16_as_ushort(h1) << 16);
        H.y = (uint32_t)__bfloat16_as_ushort(h2) | ((uint32_t)__bfloat16_as_ushort(h3) << 16);
        L.x = (uint32_t)__bfloat16_as_ushort(l0) | ((uint32_t)__bfloat16_as_ushort(l1) << 16);
        L.y = (uint32_t)__bfloat16_as_ushort(l2) | ((uint32_t)__bfloat16_as_ushort(l3) << 16);
        hi[i] = H;
        lo[i] = L;
    }
}

// ---------------------------------------------------------------------------
// Transpose + split: W [K,N] fp32 -> hi/lo [N,K] bf16
// ---------------------------------------------------------------------------
__global__ void transpose_split_kernel(const float* __restrict__ W,
                                       __nv_bfloat16* __restrict__ hi,
                                       __nv_bfloat16* __restrict__ lo,
                                       int K, int N)
{
    __shared__ float t[32][33];
    int n = blockIdx.x * 32 + threadIdx.x;
    int k = blockIdx.y * 32 + threadIdx.y;
    #pragma unroll
    for (int j = 0; j < 4; j++)
        t[threadIdx.y + j * 8][threadIdx.x] = W[(size_t)(k + j * 8) * N + n];
    __syncthreads();
    int k2 = blockIdx.y * 32 + threadIdx.x;
    int n2 = blockIdx.x * 32 + threadIdx.y;
    #pragma unroll
    for (int j = 0; j < 4; j++) {
        float v = t[threadIdx.x][threadIdx.y + j * 8];
        __nv_bfloat16 h = __float2bfloat16(v);
        hi[(size_t)(n2 + j * 8) * K + k2] = h;
        lo[(size_t)(n2 + j * 8) * K + k2] = __float2bfloat16(v - __bfloat162float(h));
    }
}

// ---------------------------------------------------------------------------
// mma.sync bf16x3 GEMM: C[M,N] = (Ahi+Alo)[M,K] @ (Bhi+Blo)[N,K]^T + bias[N]
// 128x128x32 CTA tile, 256 threads (8 warps, 2m x 4n), warp tile 64x32.
// cp.async double-buffered SMEM. Row pad to 40 bf16 (conflict-free frag LDS).
// ---------------------------------------------------------------------------
#define PAD    40
#define TBYTES (128 * PAD * 2)            // 10240 per tensor tile
#define STAGE  (4 * TBYTES)               // 40960
#define GSMEM  (2 * STAGE)                // 81920

__global__ __launch_bounds__(256) void gemm_mma_kernel(
    const __nv_bfloat16* __restrict__ Ahi,
    const __nv_bfloat16* __restrict__ Alo,
    const __nv_bfloat16* __restrict__ Bhi,
    const __nv_bfloat16* __restrict__ Blo,
    const float* __restrict__ bias,
    float* __restrict__ C,
    int M, int N, int K)
{
    extern __shared__ __align__(128) char smem[];
    const int tid  = threadIdx.x;
    const int wid  = tid >> 5;
    const int lane = tid & 31;
    const int wm   = wid & 1;            // 0..1
    const int wn   = wid >> 1;           // 0..3
    const uint32_t sbase = smem_u32(smem);

    const int row0 = blockIdx.y * 128;
    const int col0 = blockIdx.x * 128;
    const int S = K >> 5;                // k-stages of 32

    float acc[4][4][4] = {};             // [mt][nt][reg]

    // ---- stage loader (cp.async) ----
    const int lr  = tid >> 2;            // 0..63 (row, two halves via i)
    const int lc8 = (tid & 3) * 8;       // element column chunk
    auto load_stage = [&](int s) {
        const int buf = s & 1;
        const uint32_t sb = sbase + buf * STAGE;
        const int k0 = s * 32;
        #pragma unroll
        for (int i = 0; i < 2; i++) {
            int r = lr + i * 64;
            uint32_t so = sb + (uint32_t)(r * (PAD * 2) + lc8 * 2);
            size_t ga = (size_t)(row0 + r) * K + k0 + lc8;
            size_t gb = (size_t)(col0 + r) * K + k0 + lc8;
            cp_async16(so + 0 * TBYTES, Ahi + ga);
            cp_async16(so + 1 * TBYTES, Alo + ga);
            cp_async16(so + 2 * TBYTES, Bhi + gb);
            cp_async16(so + 3 * TBYTES, Blo + gb);
        }
        CP_COMMIT();
    };

    load_stage(0);

    for (int s = 0; s < S; s++) {
        if (s + 1 < S) load_stage(s + 1);
        if (s + 1 < S) { CP_WAIT(1); } else { CP_WAIT(0); }
        __syncthreads();

        const int buf = s & 1;
        const __nv_bfloat16* As = (const __nv_bfloat16*)(smem + buf * STAGE);
        const __nv_bfloat16* Al = (const __nv_bfloat16*)(smem + buf * STAGE + TBYTES);
        const __nv_bfloat16* Bs = (const __nv_bfloat16*)(smem + buf * STAGE + 2 * TBYTES);
        const __nv_bfloat16* Bl = (const __nv_bfloat16*)(smem + buf * STAGE + 3 * TBYTES);

        #pragma unroll
        for (int kk = 0; kk < 2; kk++) {
            const int kc = kk * 16 + (lane & 3) * 2;     // frag k column (lo 8)
            uint32_t ahi[4][4], alo[4][4], bhi[4][2], blo[4][2];
            #pragma unroll
            for (int mt = 0; mt < 4; mt++) {
                int r = wm * 64 + mt * 16 + (lane >> 2);
                ahi[mt][0] = *(const uint32_t*)&As[r * PAD + kc];
                ahi[mt][1] = *(const uint32_t*)&As[(r + 8) * PAD + kc];
                ahi[mt][2] = *(const uint32_t*)&As[r * PAD + kc + 8];
                ahi[mt][3] = *(const uint32_t*)&As[(r + 8) * PAD + kc + 8];
                alo[mt][0] = *(const uint32_t*)&Al[r * PAD + kc];
                alo[mt][1] = *(const uint32_t*)&Al[(r + 8) * PAD + kc];
                alo[mt][2] = *(const uint32_t*)&Al[r * PAD + kc + 8];
                alo[mt][3] = *(const uint32_t*)&Al[(r + 8) * PAD + kc + 8];
            }
            #pragma unroll
            for (int nt = 0; nt < 4; nt++) {
                int n = wn * 32 + nt * 8 + (lane >> 2);
                bhi[nt][0] = *(const uint32_t*)&Bs[n * PAD + kc];
                bhi[nt][1] = *(const uint32_t*)&Bs[n * PAD + kc + 8];
                blo[nt][0] = *(const uint32_t*)&Bl[n * PAD + kc];
                blo[nt][1] = *(const uint32_t*)&Bl[n * PAD + kc + 8];
            }
            #pragma unroll
            for (int mt = 0; mt < 4; mt++)
                #pragma unroll
                for (int nt = 0; nt < 4; nt++) {
                    mma_bf16(acc[mt][nt], ahi[mt], bhi[nt]);
                    mma_bf16(acc[mt][nt], ahi[mt], blo[nt]);
                    mma_bf16(acc[mt][nt], alo[mt], bhi[nt]);
                }
        }
        __syncthreads();
    }

    // ---- epilogue: bias + store ----
    #pragma unroll
    for (int mt = 0; mt < 4; mt++) {
        int r = row0 + wm * 64 + mt * 16 + (lane >> 2);
        #pragma unroll
        for (int nt = 0; nt < 4; nt++) {
            int c = col0 + wn * 32 + nt * 8 + (lane & 3) * 2;
            float2 bv = *(const float2*)(bias + c);
            float2 v0 = { acc[mt][nt][0] + bv.x, acc[mt][nt][1] + bv.y };
            float2 v1 = { acc[mt][nt][2] + bv.x, acc[mt][nt][3] + bv.y };
            *(float2*)(C + (size_t)r * N + c) = v0;
            *(float2*)(C + (size_t)(r + 8) * N + c) = v1;
        }
    }
}

// ---------------------------------------------------------------------------
// Causal flash attention, fp32, Dh=64, thread-per-query-row.
// Reads g_qkv fp32, writes g_attn_hi/lo (bf16 split) for the proj GEMM.
// ---------------------------------------------------------------------------
__global__ __launch_bounds__(64) void attn_kernel()
{
    __shared__ float Ks[64][64];
    __shared__ float Vs[64][64];

    const int qt = (gridDim.x - 1) - blockIdx.x;
    const int hd = blockIdx.y;
    const int b  = blockIdx.z;
    const int t  = threadIdx.x;
    const int qrow = qt * 64 + t;
    const float scale = 0.125f;

    float q[64];
    const float* qptr = g_qkv + ((size_t)(b * TLEN + qrow)) * THREEC + hd * DH;
    #pragma unroll
    for (int d = 0; d < 64; d += 4) {
        float4 v = *(const float4*)(qptr + d);
        q[d + 0] = v.x * scale;
        q[d + 1] = v.y * scale;
        q[d + 2] = v.z * scale;
        q[d + 3] = v.w * scale;
    }

    float O[64];
    #pragma unroll
    for (int d = 0; d < 64; d++) O[d] = 0.0f;
    float m = -1e30f;
    float l = 0.0f;

    for (int kt = 0; kt <= qt; kt++) {
        const float* kbase = g_qkv + ((size_t)(b * TLEN + kt * 64)) * THREEC + CDIM + hd * DH;
        const float* vbase = kbase + CDIM;
        #pragma unroll
        for (int i = 0; i < 16; i++) {
            int f = i * 64 + t;
            int r = f >> 4;
            int c = (f & 15) * 4;
            *(float4*)&Ks[r][c] = *(const float4*)(kbase + (size_t)r * THREEC + c);
            *(float4*)&Vs[r][c] = *(const float4*)(vbase + (size_t)r * THREEC + c);
        }
        __syncthreads();

        const int jmax = (kt == qt) ? t : 63;
        for (int j = 0; j <= jmax; j++) {
            float s0 = 0.f, s1 = 0.f, s2 = 0.f, s3 = 0.f;
            #pragma unroll
            for (int d = 0; d < 64; d += 16) {
                float4 k0 = *(const float4*)&Ks[j][d + 0];
                float4 k1 = *(const float4*)&Ks[j][d + 4];
                float4 k2 = *(const float4*)&Ks[j][d + 8];
                float4 k3 = *(const float4*)&Ks[j][d + 12];
                s0 += q[d + 0] * k0.x + q[d + 1] * k0.y + q[d + 2] * k0.z + q[d + 3] * k0.w;
                s1 += q[d + 4] * k1.x + q[d + 5] * k1.y + q[d + 6] * k1.z + q[d + 7] * k1.w;
                s2 += q[d + 8] * k2.x + q[d + 9] * k2.y + q[d + 10] * k2.z + q[d + 11] * k2.w;
                s3 += q[d + 12] * k3.x + q[d + 13] * k3.y + q[d + 14] * k3.z + q[d + 15] * k3.w;
            }
            float s = (s0 + s1) + (s2 + s3);

            if (s > m) {
                float alpha = __expf(m - s);
                #pragma unroll
                for (int d = 0; d < 64; d++) O[d] *= alpha;
                l *= alpha;
                m = s;
            }
            float p = __expf(s - m);
            l += p;
            #pragma unroll
            for (int d = 0; d < 64; d += 4) {
                float4 vv = *(const float4*)&Vs[j][d];
                O[d + 0] += p * vv.x;
                O[d + 1] += p * vv.y;
                O[d + 2] += p * vv.z;
                O[d + 3] += p * vv.w;
            }
        }
        __syncthreads();
    }

    const float inv = 1.0f / l;
    __nv_bfloat16 hv[64], lv[64];
    #pragma unroll
    for (int d = 0; d < 64; d++) {
        float o = O[d] * inv;
        __nv_bfloat16 h = __float2bfloat16(o);
        hv[d] = h;
        lv[d] = __float2bfloat16(o - __bfloat162float(h));
    }
    size_t off = (size_t)(b * TLEN + qrow) * CDIM + hd * DH;
    #pragma unroll
    for (int d = 0; d < 64; d += 8) {
        *(uint4*)(g_attn_hi + off + d) = *(uint4*)&hv[d];
        *(uint4*)(g_attn_lo + off + d) = *(uint4*)&lv[d];
    }
}

// ---------------------------------------------------------------------------
// kernel_launch
// ---------------------------------------------------------------------------
extern "C" void kernel_launch(void* const* d_in, const int* in_sizes, int n_in,
                              void* d_out, int out_size)
{
    const float* x     = (const float*)d_in[0];
    const float* Wqkv  = (const float*)d_in[1];
    const float* bqkv  = (const float*)d_in[2];
    const float* Wproj = (const float*)d_in[3];
    const float* bproj = (const float*)d_in[4];
    float* out = (float*)d_out;

    float* qkv_ptr;
    __nv_bfloat16 *xh, *xl, *wqh, *wql, *wph, *wpl, *ah, *al;
    cudaGetSymbolAddress((void**)&qkv_ptr, g_qkv);
    cudaGetSymbolAddress((void**)&xh, g_x_hi);
    cudaGetSymbolAddress((void**)&xl, g_x_lo);
    cudaGetSymbolAddress((void**)&wqh, g_wqkv_hi);
    cudaGetSymbolAddress((void**)&wql, g_wqkv_lo);
    cudaGetSymbolAddress((void**)&wph, g_wp_hi);
    cudaGetSymbolAddress((void**)&wpl, g_wp_lo);
    cudaGetSymbolAddress((void**)&ah, g_attn_hi);
    cudaGetSymbolAddress((void**)&al, g_attn_lo);

    cudaFuncSetAttribute(gemm_mma_kernel,
                         cudaFuncAttributeMaxDynamicSharedMemorySize, GSMEM);

    // Prep: split x; transpose+split weights
    {
        int n4 = MROWS * CDIM / 4;
        split_kernel<<<2048, 256>>>((const float4*)x, (uint2*)xh, (uint2*)xl, n4);
        transpose_split_kernel<<<dim3(THREEC / 32, CDIM / 32), dim3(32, 8)>>>(
            Wqkv, wqh, wql, CDIM, THREEC);
        transpose_split_kernel<<<dim3(CDIM / 32, CDIM / 32), dim3(32, 8)>>>(
            Wproj, wph, wpl, CDIM, CDIM);
    }

    // 1) QKV GEMM (mma.sync bf16x3): [8192,1024] @ [1024,3072] + bias -> g_qkv
    gemm_mma_kernel<<<dim3(THREEC / 128, MROWS / 128), 256, GSMEM>>>(
        xh, xl, wqh, wql, bqkv, qkv_ptr, MROWS, THREEC, CDIM);

    // 2) Causal flash attention -> g_attn_hi/lo
    attn_kernel<<<dim3(TLEN / 64, NH, BSZ), 64>>>();

    // 3) Projection GEMM: [8192,1024] @ [1024,1024] + bias -> out
    gemm_mma_kernel<<<dim3(CDIM / 128, MROWS / 128), 256, GSMEM>>>(
        ah, al, wph, wpl, bproj, out, MROWS, CDIM, CDIM);
}

// round 4
// speedup vs baseline: 2.9167x; 2.1534x over previous
#include <cuda_runtime.h>
#include <cuda_bf16.h>
#include <cstdint>
#include <cstddef>

// Problem constants
#define BSZ   4
#define TLEN  2048
#define CDIM  1024
#define NH    16
#define DH    64
#define MROWS (BSZ * TLEN)          // 8192
#define THREEC (3 * CDIM)           // 3072

// ---------------------------------------------------------------------------
// Scratch device globals
// ---------------------------------------------------------------------------
__device__ __nv_bfloat16 g_x_hi[(size_t)MROWS * CDIM];
__device__ __nv_bfloat16 g_x_lo[(size_t)MROWS * CDIM];
__device__ __nv_bfloat16 g_wqkv_hi[(size_t)THREEC * CDIM]; // W_qkv^T [N,K]
__device__ __nv_bfloat16 g_wqkv_lo[(size_t)THREEC * CDIM];
__device__ __nv_bfloat16 g_wp_hi[(size_t)CDIM * CDIM];     // W_proj^T [N,K]
__device__ __nv_bfloat16 g_wp_lo[(size_t)CDIM * CDIM];
// q,k: [b][h][t][d]; v transposed: [b][h][d][t]
__device__ __nv_bfloat16 g_qh[(size_t)MROWS * CDIM];
__device__ __nv_bfloat16 g_ql[(size_t)MROWS * CDIM];
__device__ __nv_bfloat16 g_kh[(size_t)MROWS * CDIM];
__device__ __nv_bfloat16 g_kl[(size_t)MROWS * CDIM];
__device__ __nv_bfloat16 g_vth[(size_t)MROWS * CDIM];
__device__ __nv_bfloat16 g_vtl[(size_t)MROWS * CDIM];
__device__ __nv_bfloat16 g_attn_hi[(size_t)MROWS * CDIM];  // [b*T+t][h*64+d]
__device__ __nv_bfloat16 g_attn_lo[(size_t)MROWS * CDIM];

// ---------------------------------------------------------------------------
// Helpers
// ---------------------------------------------------------------------------
__device__ __forceinline__ uint32_t smem_u32(const void* p) {
    uint32_t a;
    asm("{ .reg .u64 t; cvta.to.shared.u64 t, %1; cvt.u32.u64 %0, t; }"
        : "=r"(a) : "l"(p));
    return a;
}

__device__ __forceinline__ void cp_async16(uint32_t saddr, const void* gaddr) {
    asm volatile("cp.async.cg.shared.global [%0], [%1], 16;"
                 :: "r"(saddr), "l"(gaddr) : "memory");
}
#define CP_COMMIT() asm volatile("cp.async.commit_group;" ::: "memory")
#define CP_WAIT(n)  asm volatile("cp.async.wait_group %0;" :: "n"(n) : "memory")

__device__ __forceinline__ void mma_bf16(float* d, const uint32_t* a,
                                         uint32_t b0, uint32_t b1) {
    asm volatile(
        "mma.sync.aligned.m16n8k16.row.col.f32.bf16.bf16.f32 "
        "{%0,%1,%2,%3}, {%4,%5,%6,%7}, {%8,%9}, {%0,%1,%2,%3};"
        : "+f"(d[0]), "+f"(d[1]), "+f"(d[2]), "+f"(d[3])
        : "r"(a[0]), "r"(a[1]), "r"(a[2]), "r"(a[3]), "r"(b0), "r"(b1));
}

// split two fp32 into packed bf16x2 hi and lo words
__device__ __forceinline__ void split2(float a, float b, uint32_t& hi, uint32_t& lo) {
    __nv_bfloat16 ha = __float2bfloat16(a), hb = __float2bfloat16(b);
    __nv_bfloat16 la = __float2bfloat16(a - __bfloat162float(ha));
    __nv_bfloat16 lb = __float2bfloat16(b - __bfloat162float(hb));
    hi = (uint32_t)__bfloat16_as_ushort(ha) | ((uint32_t)__bfloat16_as_ushort(hb) << 16);
    lo = (uint32_t)__bfloat16_as_ushort(la) | ((uint32_t)__bfloat16_as_ushort(lb) << 16);
}

// ---------------------------------------------------------------------------
// Prep kernels
// ---------------------------------------------------------------------------
__global__ void split_kernel(const float4* __restrict__ in,
                             uint2* __restrict__ hi, uint2* __restrict__ lo, int n4)
{
    for (int i = blockIdx.x * blockDim.x + threadIdx.x; i < n4; i += gridDim.x * blockDim.x) {
        float4 v = in[i];
        uint2 H, L;
        split2(v.x, v.y, H.x, L.x);
        split2(v.z, v.w, H.y, L.y);
        hi[i] = H;
        lo[i] = L;
    }
}

__global__ void transpose_split_kernel(const float* __restrict__ W,
                                       __nv_bfloat16* __restrict__ hi,
                                       __nv_bfloat16* __restrict__ lo,
                                       int K, int N)
{
    __shared__ float t[32][33];
    int n = blockIdx.x * 32 + threadIdx.x;
    int k = blockIdx.y * 32 + threadIdx.y;
    #pragma unroll
    for (int j = 0; j < 4; j++)
        t[threadIdx.y + j * 8][threadIdx.x] = W[(size_t)(k + j * 8) * N + n];
    __syncthreads();
    int k2 = blockIdx.y * 32 + threadIdx.x;
    int n2 = blockIdx.x * 32 + threadIdx.y;
    #pragma unroll
    for (int j = 0; j < 4; j++) {
        float v = t[threadIdx.x][threadIdx.y + j * 8];
        __nv_bfloat16 h = __float2bfloat16(v);
        hi[(size_t)(n2 + j * 8) * K + k2] = h;
        lo[(size_t)(n2 + j * 8) * K + k2] = __float2bfloat16(v - __bfloat162float(h));
    }
}

// ---------------------------------------------------------------------------
// mma.sync bf16x3 GEMM: C = (Ahi+Alo) @ (Bhi+Blo)^T + bias
// MODE 0: fp32 store to C.   MODE 1: QKV epilogue (split + head remap).
// ---------------------------------------------------------------------------
#define PAD    40
#define TBYTES (128 * PAD * 2)
#define STAGE  (4 * TBYTES)
#define GSMEM  (2 * STAGE)

template<int MODE>
__global__ __launch_bounds__(256) void gemm_mma_kernel(
    const __nv_bfloat16* __restrict__ Ahi,
    const __nv_bfloat16* __restrict__ Alo,
    const __nv_bfloat16* __restrict__ Bhi,
    const __nv_bfloat16* __restrict__ Blo,
    const float* __restrict__ bias,
    float* __restrict__ C,
    int M, int N, int K)
{
    extern __shared__ __align__(128) char smem[];
    const int tid  = threadIdx.x;
    const int wid  = tid >> 5;
    const int lane = tid & 31;
    const int wm   = wid & 1;
    const int wn   = wid >> 1;
    const uint32_t sbase = smem_u32(smem);

    const int row0 = blockIdx.y * 128;
    const int col0 = blockIdx.x * 128;
    const int S = K >> 5;

    float acc[4][4][4] = {};

    const int lr  = tid >> 2;
    const int lc8 = (tid & 3) * 8;
    auto load_stage = [&](int s) {
        const int buf = s & 1;
        const uint32_t sb = sbase + buf * STAGE;
        const int k0 = s * 32;
        #pragma unroll
        for (int i = 0; i < 2; i++) {
            int r = lr + i * 64;
            uint32_t so = sb + (uint32_t)(r * (PAD * 2) + lc8 * 2);
            size_t ga = (size_t)(row0 + r) * K + k0 + lc8;
            size_t gb = (size_t)(col0 + r) * K + k0 + lc8;
            cp_async16(so + 0 * TBYTES, Ahi + ga);
            cp_async16(so + 1 * TBYTES, Alo + ga);
            cp_async16(so + 2 * TBYTES, Bhi + gb);
            cp_async16(so + 3 * TBYTES, Blo + gb);
        }
        CP_COMMIT();
    };

    load_stage(0);

    for (int s = 0; s < S; s++) {
        if (s + 1 < S) { load_stage(s + 1); CP_WAIT(1); } else { CP_WAIT(0); }
        __syncthreads();

        const int buf = s & 1;
        const __nv_bfloat16* As = (const __nv_bfloat16*)(smem + buf * STAGE);
        const __nv_bfloat16* Al = (const __nv_bfloat16*)(smem + buf * STAGE + TBYTES);
        const __nv_bfloat16* Bs = (const __nv_bfloat16*)(smem + buf * STAGE + 2 * TBYTES);
        const __nv_bfloat16* Bl = (const __nv_bfloat16*)(smem + buf * STAGE + 3 * TBYTES);

        #pragma unroll
        for (int kk = 0; kk < 2; kk++) {
            const int kc = kk * 16 + (lane & 3) * 2;
            uint32_t ahi[4][4], alo[4][4], bhi[4][2], blo[4][2];
            #pragma unroll
            for (int mt = 0; mt < 4; mt++) {
                int r = wm * 64 + mt * 16 + (lane >> 2);
                ahi[mt][0] = *(const uint32_t*)&As[r * PAD + kc];
                ahi[mt][1] = *(const uint32_t*)&As[(r + 8) * PAD + kc];
                ahi[mt][2] = *(const uint32_t*)&As[r * PAD + kc + 8];
                ahi[mt][3] = *(const uint32_t*)&As[(r + 8) * PAD + kc + 8];
                alo[mt][0] = *(const uint32_t*)&Al[r * PAD + kc];
                alo[mt][1] = *(const uint32_t*)&Al[(r + 8) * PAD + kc];
                alo[mt][2] = *(const uint32_t*)&Al[r * PAD + kc + 8];
                alo[mt][3] = *(const uint32_t*)&Al[(r + 8) * PAD + kc + 8];
            }
            #pragma unroll
            for (int nt = 0; nt < 4; nt++) {
                int n = wn * 32 + nt * 8 + (lane >> 2);
                bhi[nt][0] = *(const uint32_t*)&Bs[n * PAD + kc];
                bhi[nt][1] = *(const uint32_t*)&Bs[n * PAD + kc + 8];
                blo[nt][0] = *(const uint32_t*)&Bl[n * PAD + kc];
                blo[nt][1] = *(const uint32_t*)&Bl[n * PAD + kc + 8];
            }
            #pragma unroll
            for (int mt = 0; mt < 4; mt++)
                #pragma unroll
                for (int nt = 0; nt < 4; nt++) {
                    mma_bf16(acc[mt][nt], ahi[mt], bhi[nt][0], bhi[nt][1]);
                    mma_bf16(acc[mt][nt], ahi[mt], blo[nt][0], blo[nt][1]);
                    mma_bf16(acc[mt][nt], alo[mt], bhi[nt][0], bhi[nt][1]);
                }
        }
        __syncthreads();
    }

    // ---- epilogue ----
    #pragma unroll
    for (int mt = 0; mt < 4; mt++) {
        #pragma unroll
        for (int nt = 0; nt < 4; nt++) {
            int r = row0 + wm * 64 + mt * 16 + (lane >> 2);
            int c = col0 + wn * 32 + nt * 8 + (lane & 3) * 2;
            float2 bv = *(const float2*)(bias + c);
            float v00 = acc[mt][nt][0] + bv.x, v01 = acc[mt][nt][1] + bv.y;
            float v10 = acc[mt][nt][2] + bv.x, v11 = acc[mt][nt][3] + bv.y;
            if (MODE == 0) {
                *(float2*)(C + (size_t)r * N + c)       = make_float2(v00, v01);
                *(float2*)(C + (size_t)(r + 8) * N + c) = make_float2(v10, v11);
            } else {
                const int sect = c >> 10;
                const int h = (c & 1023) >> 6;
                const int d = c & 63;
                #pragma unroll
                for (int half = 0; half < 2; half++) {
                    int rr = r + half * 8;
                    float a = half ? v10 : v00;
                    float bb = half ? v11 : v01;
                    int bidx = rr >> 11, t = rr & 2047;
                    if (sect == 0) { a *= 0.125f; bb *= 0.125f; }
                    uint32_t hiw, low;
                    if (sect == 2) {
                        __nv_bfloat16 ha = __float2bfloat16(a), hb = __float2bfloat16(bb);
                        __nv_bfloat16 la = __float2bfloat16(a - __bfloat162float(ha));
                        __nv_bfloat16 lb = __float2bfloat16(bb - __bfloat162float(hb));
                        size_t vb = ((size_t)(bidx * NH + h) * 64 + d) * TLEN + t;
                        g_vth[vb] = ha; g_vth[vb + TLEN] = hb;
                        g_vtl[vb] = la; g_vtl[vb + TLEN] = lb;
                    } else {
                        split2(a, bb, hiw, low);
                        size_t qb = ((size_t)(bidx * NH + h) * TLEN + t) * 64 + d;
                        if (sect == 0) {
                            *(uint32_t*)(g_qh + qb) = hiw;
                            *(uint32_t*)(g_ql + qb) = low;
                        } else {
                            *(uint32_t*)(g_kh + qb) = hiw;
                            *(uint32_t*)(g_kl + qb) = low;
                        }
                    }
                }
            }
        }
    }
}

// ---------------------------------------------------------------------------
// Flash attention with mma.sync bf16x3. 64 queries/CTA, 4 warps.
// grid (T/64, H, B), block 128.
// ---------------------------------------------------------------------------
#define AST   72                      // bf16 elems per smem row (144B)
#define ATILE (64 * AST * 2)          // 9216 B
#define ASTAGE (4 * ATILE)            // 36864 B
#define ASMEM  (2 * ASTAGE)           // 73728 B

__global__ __launch_bounds__(128) void attn_mma_kernel()
{
    extern __shared__ __align__(128) char smem[];
    const int tid  = threadIdx.x;
    const int wid  = tid >> 5;        // 0..3
    const int lane = tid & 31;
    const uint32_t sbase = smem_u32(smem);

    const int qt = (int)(gridDim.x - 1) - (int)blockIdx.x;   // reversed
    const size_t bh = (size_t)blockIdx.z * NH + blockIdx.y;

    // ---- load Q tile (hi/lo) into stage 0, build fragments ----
    {
        #pragma unroll
        for (int i = 0; i < 4; i++) {
            int f = i * 128 + tid;
            int r = f >> 3, ch = f & 7;
            uint32_t so = sbase + (uint32_t)(r * 144 + ch * 16);
            size_t ga = ((bh * TLEN + qt * 64 + r) << 6) + ch * 8;
            cp_async16(so,         g_qh + ga);
            cp_async16(so + ATILE, g_ql + ga);
        }
        CP_COMMIT();
        CP_WAIT(0);
        __syncthreads();
    }

    uint32_t qhi[4][4], qlo[4][4];
    {
        const __nv_bfloat16* Qh = (const __nv_bfloat16*)smem;
        const __nv_bfloat16* Ql = (const __nv_bfloat16*)(smem + ATILE);
        int r = wid * 16 + (lane >> 2);
        #pragma unroll
        for (int ks = 0; ks < 4; ks++) {
            int kc = ks * 16 + (lane & 3) * 2;
            qhi[ks][0] = *(const uint32_t*)&Qh[r * AST + kc];
            qhi[ks][1] = *(const uint32_t*)&Qh[(r + 8) * AST + kc];
            qhi[ks][2] = *(const uint32_t*)&Qh[r * AST + kc + 8];
            qhi[ks][3] = *(const uint32_t*)&Qh[(r + 8) * AST + kc + 8];
            qlo[ks][0] = *(const uint32_t*)&Ql[r * AST + kc];
            qlo[ks][1] = *(const uint32_t*)&Ql[(r + 8) * AST + kc];
            qlo[ks][2] = *(const uint32_t*)&Ql[r * AST + kc + 8];
            qlo[ks][3] = *(const uint32_t*)&Ql[(r + 8) * AST + kc + 8];
        }
    }
    __syncthreads();   // done reading stage 0 as Q

    float o[8][4] = {};
    float m0 = -1e30f, m1 = -1e30f, l0 = 0.f, l1 = 0.f;

    auto load_kv = [&](int kt) {
        const uint32_t sb = sbase + (kt & 1) * ASTAGE;
        #pragma unroll
        for (int i = 0; i < 4; i++) {
            int f = i * 128 + tid;
            int r = f >> 3, ch = f & 7;
            uint32_t so = sb + (uint32_t)(r * 144 + ch * 16);
            size_t gk = ((bh * TLEN + kt * 64 + r) << 6) + ch * 8;
            size_t gv = (bh * 64 + r) * TLEN + kt * 64 + ch * 8;
            cp_async16(so + 0 * ATILE, g_kh + gk);
            cp_async16(so + 1 * ATILE, g_kl + gk);
            cp_async16(so + 2 * ATILE, g_vth + gv);
            cp_async16(so + 3 * ATILE, g_vtl + gv);
        }
        CP_COMMIT();
    };

    load_kv(0);

    for (int kt = 0; kt <= qt; kt++) {
        if (kt < qt) { load_kv(kt + 1); CP_WAIT(1); } else { CP_WAIT(0); }
        __syncthreads();

        const char* sb = smem + (kt & 1) * ASTAGE;
        const __nv_bfloat16* Kh = (const __nv_bfloat16*)(sb);
        const __nv_bfloat16* Kl = (const __nv_bfloat16*)(sb + ATILE);
        const __nv_bfloat16* Vh = (const __nv_bfloat16*)(sb + 2 * ATILE);
        const __nv_bfloat16* Vl = (const __nv_bfloat16*)(sb + 3 * ATILE);

        // ---- S = Q K^T ----
        float s[8][4] = {};
        #pragma unroll
        for (int ks = 0; ks < 4; ks++) {
            int kc = ks * 16 + (lane & 3) * 2;
            #pragma unroll
            for (int nt = 0; nt < 8; nt++) {
                int n = nt * 8 + (lane >> 2);
                uint32_t bh0 = *(const uint32_t*)&Kh[n * AST + kc];
                uint32_t bh1 = *(const uint32_t*)&Kh[n * AST + kc + 8];
                uint32_t bl0 = *(const uint32_t*)&Kl[n * AST + kc];
                uint32_t bl1 = *(const uint32_t*)&Kl[n * AST + kc + 8];
                mma_bf16(s[nt], qhi[ks], bh0, bh1);
                mma_bf16(s[nt], qhi[ks], bl0, bl1);
                mma_bf16(s[nt], qlo[ks], bh0, bh1);
            }
        }

        // ---- causal mask on diagonal tile ----
        if (kt == qt) {
            int lr0 = wid * 16 + (lane >> 2);
            #pragma unroll
            for (int nt = 0; nt < 8; nt++) {
                int lc = nt * 8 + (lane & 3) * 2;
                if (lc > lr0)         s[nt][0] = -1e30f;
                if (lc + 1 > lr0)     s[nt][1] = -1e30f;
                if (lc > lr0 + 8)     s[nt][2] = -1e30f;
                if (lc + 1 > lr0 + 8) s[nt][3] = -1e30f;
            }
        }

        // ---- online softmax ----
        float mx0 = -1e30f, mx1 = -1e30f;
        #pragma unroll
        for (int nt = 0; nt < 8; nt++) {
            mx0 = fmaxf(mx0, fmaxf(s[nt][0], s[nt][1]));
            mx1 = fmaxf(mx1, fmaxf(s[nt][2], s[nt][3]));
        }
        mx0 = fmaxf(mx0, __shfl_xor_sync(0xffffffff, mx0, 1));
        mx0 = fmaxf(mx0, __shfl_xor_sync(0xffffffff, mx0, 2));
        mx1 = fmaxf(mx1, __shfl_xor_sync(0xffffffff, mx1, 1));
        mx1 = fmaxf(mx1, __shfl_xor_sync(0xffffffff, mx1, 2));

        float mn0 = fmaxf(m0, mx0), mn1 = fmaxf(m1, mx1);
        float a0 = __expf(m0 - mn0), a1 = __expf(m1 - mn1);
        m0 = mn0; m1 = mn1;
        #pragma unroll
        for (int nt = 0; nt < 8; nt++) {
            o[nt][0] *= a0; o[nt][1] *= a0;
            o[nt][2] *= a1; o[nt][3] *= a1;
        }

        float p[8][4];
        float sum0 = 0.f, sum1 = 0.f;
        #pragma unroll
        for (int nt = 0; nt < 8; nt++) {
            p[nt][0] = __expf(s[nt][0] - m0);
            p[nt][1] = __expf(s[nt][1] - m0);
            p[nt][2] = __expf(s[nt][2] - m1);
            p[nt][3] = __expf(s[nt][3] - m1);
            sum0 += p[nt][0] + p[nt][1];
            sum1 += p[nt][2] + p[nt][3];
        }
        sum0 += __shfl_xor_sync(0xffffffff, sum0, 1);
        sum0 += __shfl_xor_sync(0xffffffff, sum0, 2);
        sum1 += __shfl_xor_sync(0xffffffff, sum1, 1);
        sum1 += __shfl_xor_sync(0xffffffff, sum1, 2);
        l0 = l0 * a0 + sum0;
        l1 = l1 * a1 + sum1;

        // ---- pack P into A fragments (hi/lo) ----
        uint32_t phi[4][4], plo[4][4];
        #pragma unroll
        for (int ks = 0; ks < 4; ks++) {
            split2(p[2 * ks][0],     p[2 * ks][1],     phi[ks][0], plo[ks][0]);
            split2(p[2 * ks][2],     p[2 * ks][3],     phi[ks][1], plo[ks][1]);
            split2(p[2 * ks + 1][0], p[2 * ks + 1][1], phi[ks][2], plo[ks][2]);
            split2(p[2 * ks + 1][2], p[2 * ks + 1][3], phi[ks][3], plo[ks][3]);
        }

        // ---- O += P V ----
        #pragma unroll
        for (int ks = 0; ks < 4; ks++) {
            int kc = ks * 16 + (lane & 3) * 2;
            #pragma unroll
            for (int dn = 0; dn < 8; dn++) {
                int n = dn * 8 + (lane >> 2);
                uint32_t vh0 = *(const uint32_t*)&Vh[n * AST + kc];
                uint32_t vh1 = *(const uint32_t*)&Vh[n * AST + kc + 8];
                uint32_t vl0 = *(const uint32_t*)&Vl[n * AST + kc];
                uint32_t vl1 = *(const uint32_t*)&Vl[n * AST + kc + 8];
                mma_bf16(o[dn], phi[ks], vh0, vh1);
                mma_bf16(o[dn], plo[ks], vh0, vh1);
                mma_bf16(o[dn], phi[ks], vl0, vl1);
            }
        }
        __syncthreads();   // all warps done with this stage before overwrite
    }

    // ---- finalize + store hi/lo split ----
    const float inv0 = 1.0f / l0;
    const float inv1 = 1.0f / l1;
    const int t0 = qt * 64 + wid * 16 + (lane >> 2);
    const size_t row0 = (size_t)blockIdx.z * TLEN + t0;
    const int colb = blockIdx.y * 64 + (lane & 3) * 2;
    #pragma unroll
    for (int dn = 0; dn < 8; dn++) {
        int col = colb + dn * 8;
        uint32_t hiw, low;
        split2(o[dn][0] * inv0, o[dn][1] * inv0, hiw, low);
        *(uint32_t*)(g_attn_hi + row0 * CDIM + col) = hiw;
        *(uint32_t*)(g_attn_lo + row0 * CDIM + col) = low;
        split2(o[dn][2] * inv1, o[dn][3] * inv1, hiw, low);
        *(uint32_t*)(g_attn_hi + (row0 + 8) * CDIM + col) = hiw;
        *(uint32_t*)(g_attn_lo + (row0 + 8) * CDIM + col) = low;
    }
}

// ---------------------------------------------------------------------------
// kernel_launch
// ---------------------------------------------------------------------------
extern "C" void kernel_launch(void* const* d_in, const int* in_sizes, int n_in,
                              void* d_out, int out_size)
{
    const float* x     = (const float*)d_in[0];
    const float* Wqkv  = (const float*)d_in[1];
    const float* bqkv  = (const float*)d_in[2];
    const float* Wproj = (const float*)d_in[3];
    const float* bproj = (const float*)d_in[4];
    float* out = (float*)d_out;

    __nv_bfloat16 *xh, *xl, *wqh, *wql, *wph, *wpl, *ah, *al;
    cudaGetSymbolAddress((void**)&xh, g_x_hi);
    cudaGetSymbolAddress((void**)&xl, g_x_lo);
    cudaGetSymbolAddress((void**)&wqh, g_wqkv_hi);
    cudaGetSymbolAddress((void**)&wql, g_wqkv_lo);
    cudaGetSymbolAddress((void**)&wph, g_wp_hi);
    cudaGetSymbolAddress((void**)&wpl, g_wp_lo);
    cudaGetSymbolAddress((void**)&ah, g_attn_hi);
    cudaGetSymbolAddress((void**)&al, g_attn_lo);

    cudaFuncSetAttribute(gemm_mma_kernel<0>,
                         cudaFuncAttributeMaxDynamicSharedMemorySize, GSMEM);
    cudaFuncSetAttribute(gemm_mma_kernel<1>,
                         cudaFuncAttributeMaxDynamicSharedMemorySize, GSMEM);
    cudaFuncSetAttribute(attn_mma_kernel,
                         cudaFuncAttributeMaxDynamicSharedMemorySize, ASMEM);

    // Prep
    {
        int n4 = MROWS * CDIM / 4;
        split_kernel<<<2048, 256>>>((const float4*)x, (uint2*)xh, (uint2*)xl, n4);
        transpose_split_kernel<<<dim3(THREEC / 32, CDIM / 32), dim3(32, 8)>>>(
            Wqkv, wqh, wql, CDIM, THREEC);
        transpose_split_kernel<<<dim3(CDIM / 32, CDIM / 32), dim3(32, 8)>>>(
            Wproj, wph, wpl, CDIM, CDIM);
    }

    // 1) QKV GEMM with fused split/remap epilogue
    gemm_mma_kernel<1><<<dim3(THREEC / 128, MROWS / 128), 256, GSMEM>>>(
        xh, xl, wqh, wql, bqkv, nullptr, MROWS, THREEC, CDIM);

    // 2) Tensor-core causal flash attention
    attn_mma_kernel<<<dim3(TLEN / 64, NH, BSZ), 128, ASMEM>>>();

    // 3) Projection GEMM
    gemm_mma_kernel<0><<<dim3(CDIM / 128, MROWS / 128), 256, GSMEM>>>(
        ah, al, wph, wpl, bproj, out, MROWS, CDIM, CDIM);
}

// round 5
// speedup vs baseline: 3.2775x; 1.1237x over previous
#include <cuda_runtime.h>
#include <cuda_bf16.h>
#include <cstdint>
#include <cstddef>

// Problem constants
#define BSZ   4
#define TLEN  2048
#define CDIM  1024
#define NH    16
#define DH    64
#define MROWS (BSZ * TLEN)          // 8192
#define THREEC (3 * CDIM)           // 3072

// ---------------------------------------------------------------------------
// Scratch device globals
// ---------------------------------------------------------------------------
__device__ __nv_bfloat16 g_x_hi[(size_t)MROWS * CDIM];
__device__ __nv_bfloat16 g_x_lo[(size_t)MROWS * CDIM];
__device__ __nv_bfloat16 g_wqkv_hi[(size_t)THREEC * CDIM]; // W_qkv^T [N,K]
__device__ __nv_bfloat16 g_wqkv_lo[(size_t)THREEC * CDIM];
__device__ __nv_bfloat16 g_wp_hi[(size_t)CDIM * CDIM];     // W_proj^T [N,K]
__device__ __nv_bfloat16 g_wp_lo[(size_t)CDIM * CDIM];
// q,k: [b][h][t][d]; v transposed: [b][h][d][t]
__device__ __nv_bfloat16 g_qh[(size_t)MROWS * CDIM];
__device__ __nv_bfloat16 g_ql[(size_t)MROWS * CDIM];
__device__ __nv_bfloat16 g_kh[(size_t)MROWS * CDIM];
__device__ __nv_bfloat16 g_kl[(size_t)MROWS * CDIM];
__device__ __nv_bfloat16 g_vth[(size_t)MROWS * CDIM];
__device__ __nv_bfloat16 g_vtl[(size_t)MROWS * CDIM];
__device__ __nv_bfloat16 g_attn_hi[(size_t)MROWS * CDIM];  // [b*T+t][h*64+d]
__device__ __nv_bfloat16 g_attn_lo[(size_t)MROWS * CDIM];

// ---------------------------------------------------------------------------
// Helpers
// ---------------------------------------------------------------------------
__device__ __forceinline__ uint32_t smem_u32(const void* p) {
    uint32_t a;
    asm("{ .reg .u64 t; cvta.to.shared.u64 t, %1; cvt.u32.u64 %0, t; }"
        : "=r"(a) : "l"(p));
    return a;
}

__device__ __forceinline__ void cp_async16(uint32_t saddr, const void* gaddr) {
    asm volatile("cp.async.cg.shared.global [%0], [%1], 16;"
                 :: "r"(saddr), "l"(gaddr) : "memory");
}
#define CP_COMMIT() asm volatile("cp.async.commit_group;" ::: "memory")
#define CP_WAIT(n)  asm volatile("cp.async.wait_group %0;" :: "n"(n) : "memory")

__device__ __forceinline__ void mma_bf16(float* d, const uint32_t* a,
                                         uint32_t b0, uint32_t b1) {
    asm volatile(
        "mma.sync.aligned.m16n8k16.row.col.f32.bf16.bf16.f32 "
        "{%0,%1,%2,%3}, {%4,%5,%6,%7}, {%8,%9}, {%0,%1,%2,%3};"
        : "+f"(d[0]), "+f"(d[1]), "+f"(d[2]), "+f"(d[3])
        : "r"(a[0]), "r"(a[1]), "r"(a[2]), "r"(a[3]), "r"(b0), "r"(b1));
}

__device__ __forceinline__ void ldsm_x4(uint32_t* r, uint32_t addr) {
    asm volatile("ldmatrix.sync.aligned.m8n8.x4.shared.b16 {%0,%1,%2,%3}, [%4];"
                 : "=r"(r[0]), "=r"(r[1]), "=r"(r[2]), "=r"(r[3]) : "r"(addr));
}

// split two fp32 into packed bf16x2 hi and lo words
__device__ __forceinline__ void split2(float a, float b, uint32_t& hi, uint32_t& lo) {
    __nv_bfloat16 ha = __float2bfloat16(a), hb = __float2bfloat16(b);
    __nv_bfloat16 la = __float2bfloat16(a - __bfloat162float(ha));
    __nv_bfloat16 lb = __float2bfloat16(b - __bfloat162float(hb));
    hi = (uint32_t)__bfloat16_as_ushort(ha) | ((uint32_t)__bfloat16_as_ushort(hb) << 16);
    lo = (uint32_t)__bfloat16_as_ushort(la) | ((uint32_t)__bfloat16_as_ushort(lb) << 16);
}

// ---------------------------------------------------------------------------
// Prep kernels
// ---------------------------------------------------------------------------
__global__ void split_kernel(const float4* __restrict__ in,
                             uint2* __restrict__ hi, uint2* __restrict__ lo, int n4)
{
    for (int i = blockIdx.x * blockDim.x + threadIdx.x; i < n4; i += gridDim.x * blockDim.x) {
        float4 v = in[i];
        uint2 H, L;
        split2(v.x, v.y, H.x, L.x);
        split2(v.z, v.w, H.y, L.y);
        hi[i] = H;
        lo[i] = L;
    }
}

__global__ void transpose_split_kernel(const float* __restrict__ W,
                                       __nv_bfloat16* __restrict__ hi,
                                       __nv_bfloat16* __restrict__ lo,
                                       int K, int N)
{
    __shared__ float t[32][33];
    int n = blockIdx.x * 32 + threadIdx.x;
    int k = blockIdx.y * 32 + threadIdx.y;
    #pragma unroll
    for (int j = 0; j < 4; j++)
        t[threadIdx.y + j * 8][threadIdx.x] = W[(size_t)(k + j * 8) * N + n];
    __syncthreads();
    int k2 = blockIdx.y * 32 + threadIdx.x;
    int n2 = blockIdx.x * 32 + threadIdx.y;
    #pragma unroll
    for (int j = 0; j < 4; j++) {
        float v = t[threadIdx.x][threadIdx.y + j * 8];
        __nv_bfloat16 h = __float2bfloat16(v);
        hi[(size_t)(n2 + j * 8) * K + k2] = h;
        lo[(size_t)(n2 + j * 8) * K + k2] = __float2bfloat16(v - __bfloat162float(h));
    }
}

// ---------------------------------------------------------------------------
// mma.sync bf16x3 GEMM: C = (Ahi+Alo) @ (Bhi+Blo)^T + bias
// MODE 0: fp32 store to C.   MODE 1: QKV epilogue (split + head remap).
// ---------------------------------------------------------------------------
#define PAD    40
#define TBYTES (128 * PAD * 2)
#define STAGE  (4 * TBYTES)
#define GSMEM  (2 * STAGE)

template<int MODE>
__global__ __launch_bounds__(256) void gemm_mma_kernel(
    const __nv_bfloat16* __restrict__ Ahi,
    const __nv_bfloat16* __restrict__ Alo,
    const __nv_bfloat16* __restrict__ Bhi,
    const __nv_bfloat16* __restrict__ Blo,
    const float* __restrict__ bias,
    float* __restrict__ C,
    int M, int N, int K)
{
    extern __shared__ __align__(128) char smem[];
    const int tid  = threadIdx.x;
    const int wid  = tid >> 5;
    const int lane = tid & 31;
    const int wm   = wid & 1;
    const int wn   = wid >> 1;
    const int lr8  = lane & 7;
    const int g    = lane >> 3;
    const uint32_t sbase = smem_u32(smem);

    const int row0 = blockIdx.y * 128;
    const int col0 = blockIdx.x * 128;
    const int S = K >> 5;

    float acc[4][4][4] = {};

    const int lr  = tid >> 2;
    const int lc8 = (tid & 3) * 8;
    auto load_stage = [&](int s) {
        const int buf = s & 1;
        const uint32_t sb = sbase + buf * STAGE;
        const int k0 = s * 32;
        #pragma unroll
        for (int i = 0; i < 2; i++) {
            int r = lr + i * 64;
            uint32_t so = sb + (uint32_t)(r * (PAD * 2) + lc8 * 2);
            size_t ga = (size_t)(row0 + r) * K + k0 + lc8;
            size_t gb = (size_t)(col0 + r) * K + k0 + lc8;
            cp_async16(so + 0 * TBYTES, Ahi + ga);
            cp_async16(so + 1 * TBYTES, Alo + ga);
            cp_async16(so + 2 * TBYTES, Bhi + gb);
            cp_async16(so + 3 * TBYTES, Blo + gb);
        }
        CP_COMMIT();
    };

    load_stage(0);

    for (int s = 0; s < S; s++) {
        if (s + 1 < S) { load_stage(s + 1); CP_WAIT(1); } else { CP_WAIT(0); }
        __syncthreads();

        const uint32_t sA = sbase + (s & 1) * STAGE;
        const uint32_t sB = sA + 2 * TBYTES;

        #pragma unroll
        for (int kk = 0; kk < 2; kk++) {
            uint32_t ahi[4][4], alo[4][4], bhi[4][2], blo[4][2];
            #pragma unroll
            for (int mt = 0; mt < 4; mt++) {
                uint32_t a = sA + (uint32_t)(((wm * 64 + mt * 16 + (g & 1) * 8 + lr8) * PAD
                                              + kk * 16 + (g >> 1) * 8) * 2);
                ldsm_x4(ahi[mt], a);
                ldsm_x4(alo[mt], a + TBYTES);
            }
            #pragma unroll
            for (int np = 0; np < 2; np++) {
                uint32_t a = sB + (uint32_t)(((wn * 32 + np * 16 + (g >> 1) * 8 + lr8) * PAD
                                              + kk * 16 + (g & 1) * 8) * 2);
                uint32_t th[4], tl[4];
                ldsm_x4(th, a);
                ldsm_x4(tl, a + TBYTES);
                bhi[2 * np][0] = th[0]; bhi[2 * np][1] = th[1];
                bhi[2 * np + 1][0] = th[2]; bhi[2 * np + 1][1] = th[3];
                blo[2 * np][0] = tl[0]; blo[2 * np][1] = tl[1];
                blo[2 * np + 1][0] = tl[2]; blo[2 * np + 1][1] = tl[3];
            }
            #pragma unroll
            for (int mt = 0; mt < 4; mt++)
                #pragma unroll
                for (int nt = 0; nt < 4; nt++) {
                    mma_bf16(acc[mt][nt], ahi[mt], bhi[nt][0], bhi[nt][1]);
                    mma_bf16(acc[mt][nt], ahi[mt], blo[nt][0], blo[nt][1]);
                    mma_bf16(acc[mt][nt], alo[mt], bhi[nt][0], bhi[nt][1]);
                }
        }
        __syncthreads();
    }

    // ---- epilogue ----
    #pragma unroll
    for (int mt = 0; mt < 4; mt++) {
        #pragma unroll
        for (int nt = 0; nt < 4; nt++) {
            int r = row0 + wm * 64 + mt * 16 + (lane >> 2);
            int c = col0 + wn * 32 + nt * 8 + (lane & 3) * 2;
            float2 bv = *(const float2*)(bias + c);
            float v00 = acc[mt][nt][0] + bv.x, v01 = acc[mt][nt][1] + bv.y;
            float v10 = acc[mt][nt][2] + bv.x, v11 = acc[mt][nt][3] + bv.y;
            if (MODE == 0) {
                *(float2*)(C + (size_t)r * N + c)       = make_float2(v00, v01);
                *(float2*)(C + (size_t)(r + 8) * N + c) = make_float2(v10, v11);
            } else {
                const int sect = c >> 10;
                const int h = (c & 1023) >> 6;
                const int d = c & 63;
                #pragma unroll
                for (int half = 0; half < 2; half++) {
                    int rr = r + half * 8;
                    float a = half ? v10 : v00;
                    float bb = half ? v11 : v01;
                    int bidx = rr >> 11, t = rr & 2047;
                    if (sect == 0) { a *= 0.125f; bb *= 0.125f; }
                    uint32_t hiw, low;
                    if (sect == 2) {
                        __nv_bfloat16 ha = __float2bfloat16(a), hb = __float2bfloat16(bb);
                        __nv_bfloat16 la = __float2bfloat16(a - __bfloat162float(ha));
                        __nv_bfloat16 lb = __float2bfloat16(bb - __bfloat162float(hb));
                        size_t vb = ((size_t)(bidx * NH + h) * 64 + d) * TLEN + t;
                        g_vth[vb] = ha; g_vth[vb + TLEN] = hb;
                        g_vtl[vb] = la; g_vtl[vb + TLEN] = lb;
                    } else {
                        split2(a, bb, hiw, low);
                        size_t qb = ((size_t)(bidx * NH + h) * TLEN + t) * 64 + d;
                        if (sect == 0) {
                            *(uint32_t*)(g_qh + qb) = hiw;
                            *(uint32_t*)(g_ql + qb) = low;
                        } else {
                            *(uint32_t*)(g_kh + qb) = hiw;
                            *(uint32_t*)(g_kl + qb) = low;
                        }
                    }
                }
            }
        }
    }
}

// ---------------------------------------------------------------------------
// Flash attention with mma.sync bf16x3 + ldmatrix. 64 queries/CTA, 4 warps.
// ---------------------------------------------------------------------------
#define AST   72                      // bf16 elems per smem row (144B)
#define ATILE (64 * AST * 2)          // 9216 B
#define ASTAGE (4 * ATILE)            // 36864 B
#define ASMEM  (2 * ASTAGE)           // 73728 B

__global__ __launch_bounds__(128) void attn_mma_kernel()
{
    extern __shared__ __align__(128) char smem[];
    const int tid  = threadIdx.x;
    const int wid  = tid >> 5;        // 0..3
    const int lane = tid & 31;
    const int lr8  = lane & 7;
    const int g    = lane >> 3;
    const uint32_t sbase = smem_u32(smem);

    const int qt = (int)(gridDim.x - 1) - (int)blockIdx.x;   // reversed
    const size_t bh = (size_t)blockIdx.z * NH + blockIdx.y;

    // ---- load Q tile (hi/lo) into stage 0, build fragments via ldmatrix ----
    {
        #pragma unroll
        for (int i = 0; i < 4; i++) {
            int f = i * 128 + tid;
            int r = f >> 3, ch = f & 7;
            uint32_t so = sbase + (uint32_t)(r * 144 + ch * 16);
            size_t ga = ((bh * TLEN + qt * 64 + r) << 6) + ch * 8;
            cp_async16(so,         g_qh + ga);
            cp_async16(so + ATILE, g_ql + ga);
        }
        CP_COMMIT();
        CP_WAIT(0);
        __syncthreads();
    }

    uint32_t qhi[4][4], qlo[4][4];
    #pragma unroll
    for (int ks = 0; ks < 4; ks++) {
        uint32_t a = sbase + (uint32_t)(((wid * 16 + (g & 1) * 8 + lr8) * AST
                                         + ks * 16 + (g >> 1) * 8) * 2);
        ldsm_x4(qhi[ks], a);
        ldsm_x4(qlo[ks], a + ATILE);
    }
    __syncthreads();   // done reading stage 0 as Q

    float o[8][4] = {};
    float m0 = -1e30f, m1 = -1e30f, l0 = 0.f, l1 = 0.f;

    auto load_kv = [&](int kt) {
        const uint32_t sb = sbase + (kt & 1) * ASTAGE;
        #pragma unroll
        for (int i = 0; i < 4; i++) {
            int f = i * 128 + tid;
            int r = f >> 3, ch = f & 7;
            uint32_t so = sb + (uint32_t)(r * 144 + ch * 16);
            size_t gk = ((bh * TLEN + kt * 64 + r) << 6) + ch * 8;
            size_t gv = (bh * 64 + r) * TLEN + kt * 64 + ch * 8;
            cp_async16(so + 0 * ATILE, g_kh + gk);
            cp_async16(so + 1 * ATILE, g_kl + gk);
            cp_async16(so + 2 * ATILE, g_vth + gv);
            cp_async16(so + 3 * ATILE, g_vtl + gv);
        }
        CP_COMMIT();
    };

    load_kv(0);

    for (int kt = 0; kt <= qt; kt++) {
        if (kt < qt) { load_kv(kt + 1); CP_WAIT(1); } else { CP_WAIT(0); }
        __syncthreads();

        const uint32_t sbK = sbase + (kt & 1) * ASTAGE;
        const uint32_t sbV = sbK + 2 * ATILE;

        // ---- S = Q K^T ----
        float s[8][4] = {};
        #pragma unroll
        for (int ks = 0; ks < 4; ks++) {
            #pragma unroll
            for (int np = 0; np < 4; np++) {
                uint32_t a = sbK + (uint32_t)(((np * 16 + (g >> 1) * 8 + lr8) * AST
                                               + ks * 16 + (g & 1) * 8) * 2);
                uint32_t kh4[4], kl4[4];
                ldsm_x4(kh4, a);
                ldsm_x4(kl4, a + ATILE);
                mma_bf16(s[2 * np],     qhi[ks], kh4[0], kh4[1]);
                mma_bf16(s[2 * np],     qhi[ks], kl4[0], kl4[1]);
                mma_bf16(s[2 * np],     qlo[ks], kh4[0], kh4[1]);
                mma_bf16(s[2 * np + 1], qhi[ks], kh4[2], kh4[3]);
                mma_bf16(s[2 * np + 1], qhi[ks], kl4[2], kl4[3]);
                mma_bf16(s[2 * np + 1], qlo[ks], kh4[2], kh4[3]);
            }
        }

        // ---- causal mask on diagonal tile ----
        if (kt == qt) {
            int lrow = wid * 16 + (lane >> 2);
            #pragma unroll
            for (int nt = 0; nt < 8; nt++) {
                int lc = nt * 8 + (lane & 3) * 2;
                if (lc > lrow)         s[nt][0] = -1e30f;
                if (lc + 1 > lrow)     s[nt][1] = -1e30f;
                if (lc > lrow + 8)     s[nt][2] = -1e30f;
                if (lc + 1 > lrow + 8) s[nt][3] = -1e30f;
            }
        }

        // ---- online softmax ----
        float mx0 = -1e30f, mx1 = -1e30f;
        #pragma unroll
        for (int nt = 0; nt < 8; nt++) {
            mx0 = fmaxf(mx0, fmaxf(s[nt][0], s[nt][1]));
            mx1 = fmaxf(mx1, fmaxf(s[nt][2], s[nt][3]));
        }
        mx0 = fmaxf(mx0, __shfl_xor_sync(0xffffffff, mx0, 1));
        mx0 = fmaxf(mx0, __shfl_xor_sync(0xffffffff, mx0, 2));
        mx1 = fmaxf(mx1, __shfl_xor_sync(0xffffffff, mx1, 1));
        mx1 = fmaxf(mx1, __shfl_xor_sync(0xffffffff, mx1, 2));

        float mn0 = fmaxf(m0, mx0), mn1 = fmaxf(m1, mx1);
        float a0 = __expf(m0 - mn0), a1 = __expf(m1 - mn1);
        m0 = mn0; m1 = mn1;
        #pragma unroll
        for (int nt = 0; nt < 8; nt++) {
            o[nt][0] *= a0; o[nt][1] *= a0;
            o[nt][2] *= a1; o[nt][3] *= a1;
        }

        float p[8][4];
        float sum0 = 0.f, sum1 = 0.f;
        #pragma unroll
        for (int nt = 0; nt < 8; nt++) {
            p[nt][0] = __expf(s[nt][0] - m0);
            p[nt][1] = __expf(s[nt][1] - m0);
            p[nt][2] = __expf(s[nt][2] - m1);
            p[nt][3] = __expf(s[nt][3] - m1);
            sum0 += p[nt][0] + p[nt][1];
            sum1 += p[nt][2] + p[nt][3];
        }
        sum0 += __shfl_xor_sync(0xffffffff, sum0, 1);
        sum0 += __shfl_xor_sync(0xffffffff, sum0, 2);
        sum1 += __shfl_xor_sync(0xffffffff, sum1, 1);
        sum1 += __shfl_xor_sync(0xffffffff, sum1, 2);
        l0 = l0 * a0 + sum0;
        l1 = l1 * a1 + sum1;

        // ---- pack P into A fragments (hi/lo) ----
        uint32_t phi[4][4], plo[4][4];
        #pragma unroll
        for (int ks = 0; ks < 4; ks++) {
            split2(p[2 * ks][0],     p[2 * ks][1],     phi[ks][0], plo[ks][0]);
            split2(p[2 * ks][2],     p[2 * ks][3],     phi[ks][1], plo[ks][1]);
            split2(p[2 * ks + 1][0], p[2 * ks + 1][1], phi[ks][2], plo[ks][2]);
            split2(p[2 * ks + 1][2], p[2 * ks + 1][3], phi[ks][3], plo[ks][3]);
        }

        // ---- O += P V ----
        #pragma unroll
        for (int ks = 0; ks < 4; ks++) {
            #pragma unroll
            for (int np = 0; np < 4; np++) {
                uint32_t a = sbV + (uint32_t)(((np * 16 + (g >> 1) * 8 + lr8) * AST
                                               + ks * 16 + (g & 1) * 8) * 2);
                uint32_t vh4[4], vl4[4];
                ldsm_x4(vh4, a);
                ldsm_x4(vl4, a + ATILE);
                mma_bf16(o[2 * np],     phi[ks], vh4[0], vh4[1]);
                mma_bf16(o[2 * np],     plo[ks], vh4[0], vh4[1]);
                mma_bf16(o[2 * np],     phi[ks], vl4[0], vl4[1]);
                mma_bf16(o[2 * np + 1], phi[ks], vh4[2], vh4[3]);
                mma_bf16(o[2 * np + 1], plo[ks], vh4[2], vh4[3]);
                mma_bf16(o[2 * np + 1], phi[ks], vl4[2], vl4[3]);
            }
        }
        __syncthreads();
    }

    // ---- finalize + store hi/lo split ----
    const float inv0 = 1.0f / l0;
    const float inv1 = 1.0f / l1;
    const int t0 = qt * 64 + wid * 16 + (lane >> 2);
    const size_t row0 = (size_t)blockIdx.z * TLEN + t0;
    const int colb = blockIdx.y * 64 + (lane & 3) * 2;
    #pragma unroll
    for (int dn = 0; dn < 8; dn++) {
        int col = colb + dn * 8;
        uint32_t hiw, low;
        split2(o[dn][0] * inv0, o[dn][1] * inv0, hiw, low);
        *(uint32_t*)(g_attn_hi + row0 * CDIM + col) = hiw;
        *(uint32_t*)(g_attn_lo + row0 * CDIM + col) = low;
        split2(o[dn][2] * inv1, o[dn][3] * inv1, hiw, low);
        *(uint32_t*)(g_attn_hi + (row0 + 8) * CDIM + col) = hiw;
        *(uint32_t*)(g_attn_lo + (row0 + 8) * CDIM + col) = low;
    }
}

// ---------------------------------------------------------------------------
// kernel_launch
// ---------------------------------------------------------------------------
extern "C" void kernel_launch(void* const* d_in, const int* in_sizes, int n_in,
                              void* d_out, int out_size)
{
    const float* x     = (const float*)d_in[0];
    const float* Wqkv  = (const float*)d_in[1];
    const float* bqkv  = (const float*)d_in[2];
    const float* Wproj = (const float*)d_in[3];
    const float* bproj = (const float*)d_in[4];
    float* out = (float*)d_out;

    __nv_bfloat16 *xh, *xl, *wqh, *wql, *wph, *wpl, *ah, *al;
    cudaGetSymbolAddress((void**)&xh, g_x_hi);
    cudaGetSymbolAddress((void**)&xl, g_x_lo);
    cudaGetSymbolAddress((void**)&wqh, g_wqkv_hi);
    cudaGetSymbolAddress((void**)&wql, g_wqkv_lo);
    cudaGetSymbolAddress((void**)&wph, g_wp_hi);
    cudaGetSymbolAddress((void**)&wpl, g_wp_lo);
    cudaGetSymbolAddress((void**)&ah, g_attn_hi);
    cudaGetSymbolAddress((void**)&al, g_attn_lo);

    cudaFuncSetAttribute(gemm_mma_kernel<0>,
                         cudaFuncAttributeMaxDynamicSharedMemorySize, GSMEM);
    cudaFuncSetAttribute(gemm_mma_kernel<1>,
                         cudaFuncAttributeMaxDynamicSharedMemorySize, GSMEM);
    cudaFuncSetAttribute(attn_mma_kernel,
                         cudaFuncAttributeMaxDynamicSharedMemorySize, ASMEM);

    // Prep
    {
        int n4 = MROWS * CDIM / 4;
        split_kernel<<<2048, 256>>>((const float4*)x, (uint2*)xh, (uint2*)xl, n4);
        transpose_split_kernel<<<dim3(THREEC / 32, CDIM / 32), dim3(32, 8)>>>(
            Wqkv, wqh, wql, CDIM, THREEC);
        transpose_split_kernel<<<dim3(CDIM / 32, CDIM / 32), dim3(32, 8)>>>(
            Wproj, wph, wpl, CDIM, CDIM);
    }

    // 1) QKV GEMM with fused split/remap epilogue
    gemm_mma_kernel<1><<<dim3(THREEC / 128, MROWS / 128), 256, GSMEM>>>(
        xh, xl, wqh, wql, bqkv, nullptr, MROWS, THREEC, CDIM);

    // 2) Tensor-core causal flash attention
    attn_mma_kernel<<<dim3(TLEN / 64, NH, BSZ), 128, ASMEM>>>();

    // 3) Projection GEMM
    gemm_mma_kernel<0><<<dim3(CDIM / 128, MROWS / 128), 256, GSMEM>>>(
        ah, al, wph, wpl, bproj, out, MROWS, CDIM, CDIM);
}